// round 2
// baseline (speedup 1.0000x reference)
#include <cuda_runtime.h>
#include <math.h>

#define NNODES 65536
#define DF 64
#define NEDGES 1048576

// 16 MB scratch for irc = alpha*feature + (1-alpha)*agg (static: no allocs allowed)
__device__ float g_irc[NNODES * DF];

// ---------------------------------------------------------------------------
// Kernel 1: irc[i][j] = alpha * feature[i][j]   (vectorized float4)
// ---------------------------------------------------------------------------
__global__ void k_init(const float* __restrict__ feature,
                       const float* __restrict__ alpha_p) {
    const float alpha = __ldg(alpha_p);
    int i = blockIdx.x * blockDim.x + threadIdx.x;   // float4 index
    float4 f = __ldg(((const float4*)feature) + i);
    float4 r;
    r.x = alpha * f.x; r.y = alpha * f.y; r.z = alpha * f.z; r.w = alpha * f.w;
    ((float4*)g_irc)[i] = r;
}

// ---------------------------------------------------------------------------
// Kernel 2: edge scatter. 16 threads per edge, each thread owns one float4
// quad. irc[dst] += (1-alpha)*val * x[src]  via red.global.add.v4.f32.
// x (16 MB) and irc (16 MB) both fit in L2 -> gathers and atomics are L2 ops.
// ---------------------------------------------------------------------------
__global__ void k_scatter(const float* __restrict__ x,
                          const int*   __restrict__ src,
                          const int*   __restrict__ dst,
                          const float* __restrict__ val,
                          const float* __restrict__ alpha_p) {
    const int t = blockIdx.x * blockDim.x + threadIdx.x;
    const int e = t >> 4;          // edge index
    const int q = t & 15;          // quad index within row (q*4 .. q*4+3)
    if (e >= NEDGES) return;

    const float w = (1.0f - __ldg(alpha_p)) * __ldg(val + e);
    const int   s = __ldg(src + e);
    const int   d = __ldg(dst + e);

    float4 xv = __ldg(((const float4*)(x + (size_t)s * DF)) + q);
    float* p  = g_irc + (size_t)d * DF + q * 4;
    asm volatile("red.global.add.v4.f32 [%0], {%1, %2, %3, %4};"
                 :: "l"(p), "f"(w * xv.x), "f"(w * xv.y),
                    "f"(w * xv.z), "f"(w * xv.w)
                 : "memory");
}

// ---------------------------------------------------------------------------
// Kernel 3: out = (1-beta)*irc + beta*(irc @ W), W is 64x64.
// Block = 256 threads = 4 node-lanes x 64 columns. Each thread holds its
// column of W in 64 registers; irc rows staged in shared (broadcast reads).
// ---------------------------------------------------------------------------
__global__ void k_gemm(const float* __restrict__ weight,
                       const float* __restrict__ lamda_p,
                       const int*   __restrict__ l_p,
                       float*       __restrict__ out) {
    __shared__ float Ws[DF * DF];     // 16 KB
    __shared__ float ircs[4][DF];     // 1 KB

    const int j   = threadIdx.x & 63;   // output column
    const int sub = threadIdx.x >> 6;   // node-lane within block (0..3)

    for (int i = threadIdx.x; i < DF * DF; i += blockDim.x)
        Ws[i] = weight[i];
    __syncthreads();

    float wcol[DF];
#pragma unroll
    for (int k = 0; k < DF; k++) wcol[k] = Ws[k * DF + j];

    const float lam = __ldg(lamda_p);
    const int   l   = (l_p != nullptr) ? __ldg(l_p) : 1;
    const float beta = logf(lam / (float)l + 1.0f);
    const float omb  = 1.0f - beta;

    for (int base = blockIdx.x * 4; base < NNODES; base += gridDim.x * 4) {
        const int node = base + sub;
        __syncthreads();                         // protect prior iter readers
        ircs[sub][j] = g_irc[(size_t)node * DF + j];
        __syncthreads();

        float acc = 0.0f;
#pragma unroll
        for (int k = 0; k < DF; k++)
            acc = fmaf(ircs[sub][k], wcol[k], acc);

        out[(size_t)node * DF + j] = omb * ircs[sub][j] + beta * acc;
    }
}

// ---------------------------------------------------------------------------
// Launch. Input order (metadata): feature, x, adj_src, adj_dst, adj_val,
// weight, alpha, lamda, l. Output: float32 [N, D].
// ---------------------------------------------------------------------------
extern "C" void kernel_launch(void* const* d_in, const int* in_sizes, int n_in,
                              void* d_out, int out_size) {
    const float* feature = (const float*)d_in[0];
    const float* x       = (const float*)d_in[1];
    const int*   adj_src = (const int*)  d_in[2];
    const int*   adj_dst = (const int*)  d_in[3];
    const float* adj_val = (const float*)d_in[4];
    const float* weight  = (const float*)d_in[5];
    const float* alpha   = (const float*)d_in[6];
    const float* lamda   = (const float*)d_in[7];
    const int*   l_p     = (n_in >= 9) ? (const int*)d_in[8] : nullptr;
    float* out = (float*)d_out;
    (void)in_sizes; (void)out_size;

    // 1) init: 65536*64/4 = 1,048,576 float4 elements
    k_init<<<(NNODES * DF / 4) / 256, 256>>>(feature, alpha);

    // 2) scatter: 1M edges * 16 threads = 16M threads
    k_scatter<<<(NEDGES * 16) / 256, 256>>>(x, adj_src, adj_dst, adj_val, alpha);

    // 3) epilogue GEMM: persistent-ish grid, 4 nodes per block per iteration
    k_gemm<<<2048, 256>>>(weight, lamda, l_p, out);
}